// round 10
// baseline (speedup 1.0000x reference)
#include <cuda_runtime.h>
#include <cuda_fp16.h>
#include <math.h>

#define N_ENT 100000
#define N_USR 50000
#define N_TOT 150000
#define DIM 64
#define E_KG 1500000
#define E_CF 1500000
#define LEAKY 0.01f

#define NB_KG 98    // ceil(100000/1024)
#define NB_AIN 147  // ceil(150000/1024)
#define NBF 1563    // ceil(100000/64)

#define B_H 11719   // ceil(3,000,000/256) edge hist
#define B_I 9375    // N_TOT*16/256 init float4
#define B_P 9       // PQ + cr
#define B_S 2       // spine zero
#define B_ATBT 1563

// ---------------- scratch (static device globals; zero-initialized at load) ----------------
__device__ float d_PQ[128 * 16];
__device__ float d_cr[16];
__device__ float d_At[(size_t)N_ENT * 16];
__device__ float d_Bt[(size_t)N_ENT * 16];
__device__ int   d_kg_cnt[N_ENT];
__device__ int   d_kg_rp[N_ENT + 1];
__device__ int2  d_csr_kg[E_KG];            // (tail*128 byte-offset, half2(a,a) bits)
__device__ int   d_ain_cnt[N_TOT];
__device__ int   d_ain_rp[N_TOT + 1];
__device__ int2  d_csr_ain[E_CF];           // (col*128 byte-offset, half2(v,v) bits)
__device__ unsigned short d_rank[E_KG + E_CF];  // within-row rank from hist
__device__ unsigned d_spine[512];
__device__ __align__(16) __half2 d_kg16[2][(size_t)N_ENT * 32];  // fp16 gather source (kg)
__device__ __align__(16) __half2 d_xy16[2][(size_t)N_TOT * 32];  // fp16 gather source (ain)
__device__ float d_ig[(size_t)N_TOT * DIM];                      // fp32 ain-spmm out
__device__ float d_sum[(size_t)N_TOT * DIM];

// ---------------- helpers ----------------
__device__ __forceinline__ void fma2(unsigned long long& d, unsigned long long a,
                                     unsigned long long b) {
    asm("fma.rn.f32x2 %0, %1, %2, %0;" : "+l"(d) : "l"(a), "l"(b));
}
__device__ __forceinline__ unsigned long long splat2(float x) {
    unsigned long long r;
    asm("mov.b64 %0, {%1, %1};" : "=l"(r) : "r"(__float_as_uint(x)));
    return r;
}
__device__ __forceinline__ void unpack2(unsigned long long v, float& lo, float& hi) {
    unsigned a, b;
    asm("mov.b64 {%0, %1}, %2;" : "=r"(a), "=r"(b) : "l"(v));
    lo = __uint_as_float(a);
    hi = __uint_as_float(b);
}
__device__ __forceinline__ uint2 pack_h4(float a, float b, float c, float d) {
    __half2 h0 = __floats2half2_rn(a, b);
    __half2 h1 = __floats2half2_rn(c, d);
    uint2 u;
    u.x = *(unsigned*)&h0;
    u.y = *(unsigned*)&h1;
    return u;
}
__device__ __forceinline__ __half2 u2h(unsigned u) { return *(__half2*)&u; }
__device__ __forceinline__ unsigned h2u(__half2 h) { return *(unsigned*)&h; }

// ====== Launch 0: hist(+rank) + init copies + PQ/cr + spine zero (all independent) ======
__global__ void k_setup(const float* __restrict__ E0, const float* __restrict__ Wk,
                        const float* __restrict__ Wkb, const float* __restrict__ rel,
                        const int* __restrict__ kgh, const int* __restrict__ ar) {
    int b = blockIdx.x, tid = threadIdx.x;
    if (b < B_H) {
        int e = b * 256 + tid;
        if (e < E_KG) {
            int p = atomicAdd(&d_kg_cnt[kgh[e]], 1);
            d_rank[e] = (unsigned short)p;
        } else {
            int e2 = e - E_KG;
            if (e2 < E_CF) {
                int p = atomicAdd(&d_ain_cnt[ar[e2]], 1);
                d_rank[e] = (unsigned short)p;
            }
        }
    } else if (b < B_H + B_I) {
        int i = (b - B_H) * 256 + tid;   // exactly N_TOT*16 float4s
        float4 v = ((const float4*)E0)[i];
        ((float4*)d_sum)[i] = v;
        uint2 u = pack_h4(v.x, v.y, v.z, v.w);
        ((uint2*)d_xy16[0])[i] = u;
        if (i < N_ENT * 16) ((uint2*)d_kg16[0])[i] = u;
    } else if (b < B_H + B_I + B_P) {
        int j = (b - B_H - B_I) * 256 + tid;
        if (j < 2048) {
            int jj = j >> 4, r = j & 15;
            float s = 0.f;
            #pragma unroll
            for (int d = 0; d < 64; d++) s += Wk[jj * 64 + d] * rel[r * 64 + d];
            d_PQ[jj * 16 + r] = s;
        } else if (j < 2064) {
            int r = j - 2048;
            float s = 0.f;
            #pragma unroll
            for (int d = 0; d < 64; d++) s += Wkb[d] * rel[r * 64 + d];
            d_cr[r] = s;
        }
    } else {
        int i = (b - B_H - B_I - B_P) * 256 + tid;
        if (i < 512) d_spine[i] = 0u;
    }
}

// ================= Launch 1: At/Bt precompute + single-pass lookback scans ================
__global__ void __launch_bounds__(1024) k_atbt_scan(const float* __restrict__ E0) {
    __shared__ float sm[6144];
    int t = threadIdx.x;
    if (blockIdx.x < B_ATBT) {
        float* sPQ = sm;
        float* sE = sm + 2048;
        int nb = blockIdx.x * 64;
        for (int i = t; i < 2048; i += 1024) sPQ[i] = d_PQ[i];
        for (int i = t; i < 4096; i += 1024) {
            int rr = nb + (i >> 6);
            sE[i] = (rr < N_ENT) ? E0[(size_t)rr * 64 + (i & 63)] : 0.f;
        }
        __syncthreads();
        int ln = t >> 4, r = t & 15;
        float a = 0.f, bb = 0.f;
        #pragma unroll
        for (int j = 0; j < 64; j++) {
            float e = sE[ln * 64 + j];
            a += e * sPQ[j * 16 + r];
            bb += e * sPQ[(64 + j) * 16 + r];
        }
        int n = nb + ln;
        if (n < N_ENT) {
            d_At[(size_t)n * 16 + r] = a;
            d_Bt[(size_t)n * 16 + r] = bb;
        }
        return;
    }
    int b2 = blockIdx.x - B_ATBT;
    int which = (b2 >= NB_KG);
    int b = which ? b2 - NB_KG : b2;
    int* cnt = which ? d_ain_cnt : d_kg_cnt;
    int* rp = which ? d_ain_rp : d_kg_rp;
    int N = which ? N_TOT : N_ENT;
    int base = which ? 256 : 0;
    int* sh = (int*)sm;
    int i = b * 1024 + t;
    int v = (i < N) ? cnt[i] : 0;
    sh[t] = v;
    __syncthreads();
    for (int s = 1; s < 1024; s <<= 1) {
        int x = (t >= s) ? sh[t - s] : 0;
        __syncthreads();
        sh[t] += x;
        __syncthreads();
    }
    int agg = sh[1023];
    __shared__ int s_ex;
    if (t == 0) {
        volatile unsigned* sp = d_spine;
        if (b == 0) {
            __threadfence();
            sp[base] = (2u << 30) | (unsigned)agg;
            s_ex = 0;
        } else {
            __threadfence();
            sp[base + b] = (1u << 30) | (unsigned)agg;
            int ex = 0;
            int p = b - 1;
            while (true) {
                unsigned w;
                do { w = sp[base + p]; } while ((w >> 30) == 0u);
                ex += (int)(w & 0x3FFFFFFFu);
                if ((w >> 30) == 2u) break;
                p--;
            }
            __threadfence();
            sp[base + b] = (2u << 30) | (unsigned)(ex + agg);
            s_ex = ex;
        }
    }
    __syncthreads();
    int ex = s_ex;
    if (i < N) rp[i + 1] = ex + sh[t];
    if (b == 0 && t == 0) rp[0] = 0;
}

// ========== Launch 2: atomic-free scatter (p = rp[key] + rank[e]) ==========
__global__ void k_scatter(const int* __restrict__ h, const int* __restrict__ tt_,
                          const int* __restrict__ r, const int* __restrict__ ar,
                          const int* __restrict__ ac, const float* __restrict__ av) {
    int e = blockIdx.x * blockDim.x + threadIdx.x;
    if (e < E_KG) {
        int hh = h[e], tt = tt_[e], rr = r[e];
        float l = d_At[(size_t)tt * 16 + rr] + d_Bt[(size_t)hh * 16 + rr] + d_cr[rr];
        l = (l >= 0.f) ? l : LEAKY * l;
        float ex = __expf(l);   // logits ~ N(0, 1/8): no max-subtraction needed
        int p = d_kg_rp[hh] + (int)d_rank[e];
        d_csr_kg[p] = make_int2(tt * 128, (int)h2u(__float2half2_rn(ex)));
    } else {
        int e2 = e - E_KG;
        if (e2 >= E_CF) return;
        int p = d_ain_rp[ar[e2]] + (int)d_rank[e];
        d_csr_ain[p] = make_int2(ac[e2] * 128, (int)h2u(__float2half2_rn(av[e2])));
    }
}

// ===== Launches 3,5,7: merged SpMM — 2 rows/warp, HFMA2, in-kernel softmax denominator ====
__global__ void __launch_bounds__(256) k_spmm(int cur) {
    int gw = (blockIdx.x * 256 + threadIdx.x) >> 5;
    int lane = threadIdx.x & 31;
    int l16 = lane & 15;
    int half = lane >> 4;
    const __half2* __restrict__ X16;
    const int2* __restrict__ csr;
    const int* __restrict__ rp;
    int row;
    bool iskg = (gw < N_ENT / 2);
    if (iskg) {
        X16 = d_kg16[cur];
        csr = d_csr_kg;
        rp = d_kg_rp;
        row = gw * 2 + half;
    } else {
        int w = gw - N_ENT / 2;
        X16 = d_xy16[cur];
        csr = d_csr_ain;
        rp = d_ain_rp;
        row = w * 2 + half;
    }
    int s = rp[row], e = rp[row + 1];
    int G = (e - s + 15) >> 4;
    int Gmax = __reduce_max_sync(0xffffffffu, G);
    float ac0 = 0.f, ac1 = 0.f, ac2 = 0.f, ac3 = 0.f;
    float asum = 0.f;                 // row softmax denominator (kg only)
    const char* Xb = (const char*)X16;
    int loff = l16 * 8;
    const __half2 hz = __floats2half2_rn(0.f, 0.f);
    for (int g = 0; g < Gmax; g++) {
        int idx = s + g * 16 + l16;
        int off = 0;
        unsigned ab = 0;              // half2(0,0)
        if (idx < e) {
            int2 ev = csr[idx];
            off = ev.x;
            ab = (unsigned)ev.y;
        }
        asum += __low2float(u2h(ab));
        int n = e - s - g * 16;
        n = max(0, min(16, n));
        int nr = __reduce_max_sync(0xffffffffu, (n + 3) & ~3);
        __half2 h0 = hz, h1 = hz, h2 = hz, h3 = hz;
        for (int j = 0; j < nr; j += 4) {
            int o0 = __shfl_sync(~0u, off, j + 0, 16), o1 = __shfl_sync(~0u, off, j + 1, 16);
            int o2 = __shfl_sync(~0u, off, j + 2, 16), o3 = __shfl_sync(~0u, off, j + 3, 16);
            unsigned b0 = __shfl_sync(~0u, ab, j + 0, 16), b1 = __shfl_sync(~0u, ab, j + 1, 16);
            unsigned b2 = __shfl_sync(~0u, ab, j + 2, 16), b3 = __shfl_sync(~0u, ab, j + 3, 16);
            uint2 r0 = *(const uint2*)(Xb + o0 + loff);
            uint2 r1 = *(const uint2*)(Xb + o1 + loff);
            uint2 r2 = *(const uint2*)(Xb + o2 + loff);
            uint2 r3 = *(const uint2*)(Xb + o3 + loff);
            h0 = __hfma2(u2h(b0), u2h(r0.x), h0);
            h1 = __hfma2(u2h(b0), u2h(r0.y), h1);
            h2 = __hfma2(u2h(b1), u2h(r1.x), h2);
            h3 = __hfma2(u2h(b1), u2h(r1.y), h3);
            h0 = __hfma2(u2h(b2), u2h(r2.x), h0);
            h1 = __hfma2(u2h(b2), u2h(r2.y), h1);
            h2 = __hfma2(u2h(b3), u2h(r3.x), h2);
            h3 = __hfma2(u2h(b3), u2h(r3.y), h3);
        }
        // flush half partials (<=8-term chains) into fp32 accumulators
        float2 f0 = __half22float2(h0), f1 = __half22float2(h1);
        float2 f2 = __half22float2(h2), f3 = __half22float2(h3);
        ac0 += f0.x + f2.x;
        ac1 += f0.y + f2.y;
        ac2 += f1.x + f3.x;
        ac3 += f1.y + f3.y;
    }
    if (iskg) {
        #pragma unroll
        for (int o = 1; o < 16; o <<= 1) asum += __shfl_xor_sync(~0u, asum, o, 16);
        float sc = (e > s) ? 1.f / asum : 0.f;   // fold softmax normalization
        ac0 *= sc; ac1 *= sc; ac2 *= sc; ac3 *= sc;
        *(uint2*)((char*)d_kg16[cur ^ 1] + (size_t)row * 128 + loff) =
            pack_h4(ac0, ac1, ac2, ac3);
    } else {
        *(float4*)(d_ig + (size_t)row * 64 + l16 * 4) = make_float4(ac0, ac1, ac2, ac3);
    }
}

// ===== Launches 4,6,8: fusion gate (items, f32x2) + user pass-through =====
__global__ void k_fusion_users(const float* __restrict__ Wa, const float* __restrict__ Wb,
                               int cur) {
    if (blockIdx.x >= NBF) {
        int i = (blockIdx.x - NBF) * 256 + threadIdx.x;
        if (i >= N_USR * 16) return;
        const float4* src = (const float4*)(d_ig + (size_t)N_ENT * 64);
        float4 v = src[i];
        ((uint2*)(d_xy16[cur ^ 1] + (size_t)N_ENT * 32))[i] = pack_h4(v.x, v.y, v.z, v.w);
        float4* as = (float4*)(d_sum + (size_t)N_ENT * 64);
        float4 a = as[i];
        a.x += v.x; a.y += v.y; a.z += v.z; a.w += v.w;
        as[i] = a;
        return;
    }
    __shared__ float sKG[64][68];
    __shared__ float sIG[64][68];
    const char* __restrict__ KG16 = (const char*)d_kg16[cur ^ 1];
    const float* __restrict__ IG = d_ig;
    int row0 = blockIdx.x * 64;
    int tid = threadIdx.x;  // 256
    for (int i = tid; i < 1024; i += 256) {
        int r = i >> 4, c4 = (i & 15) * 4;
        int gr = row0 + r;
        float4 kgv = make_float4(0.f, 0.f, 0.f, 0.f), igv = kgv;
        if (gr < N_ENT) {
            uint2 u = *(const uint2*)(KG16 + (size_t)gr * 128 + (i & 15) * 8);
            float2 fa = __half22float2(u2h(u.x)), fb = __half22float2(u2h(u.y));
            kgv = make_float4(fa.x, fa.y, fb.x, fb.y);
            igv = *(const float4*)(IG + (size_t)gr * 64 + c4);
        }
        *(float4*)&sKG[r][c4] = kgv;
        *(float4*)&sIG[r][c4] = igv;
    }
    __syncthreads();
    int tx = tid & 15, ty = tid >> 4;
    unsigned long long acc[4][2];
    #pragma unroll
    for (int i = 0; i < 4; i++) { acc[i][0] = 0ull; acc[i][1] = 0ull; }
    const float4* WaP = (const float4*)(Wa + tx * 4);
    const float4* WbP = (const float4*)(Wb + tx * 4);
    #pragma unroll
    for (int k4 = 0; k4 < 64; k4 += 4) {
        float4 kg[4], ig[4];
        #pragma unroll
        for (int i = 0; i < 4; i++) {
            kg[i] = *(const float4*)&sKG[ty * 4 + i][k4];
            ig[i] = *(const float4*)&sIG[ty * 4 + i][k4];
        }
        #pragma unroll
        for (int kk = 0; kk < 4; kk++) {
            float4 wav = WaP[(k4 + kk) * 16];
            float4 wbv = WbP[(k4 + kk) * 16];
            unsigned long long wa0, wa1, wb0, wb1;
            asm("mov.b64 %0, {%1, %2};" : "=l"(wa0) : "f"(wav.x), "f"(wav.y));
            asm("mov.b64 %0, {%1, %2};" : "=l"(wa1) : "f"(wav.z), "f"(wav.w));
            asm("mov.b64 %0, {%1, %2};" : "=l"(wb0) : "f"(wbv.x), "f"(wbv.y));
            asm("mov.b64 %0, {%1, %2};" : "=l"(wb1) : "f"(wbv.z), "f"(wbv.w));
            #pragma unroll
            for (int i = 0; i < 4; i++) {
                unsigned long long ks = splat2(((const float*)&kg[i])[kk]);
                unsigned long long is2 = splat2(((const float*)&ig[i])[kk]);
                fma2(acc[i][0], ks, wa0);
                fma2(acc[i][1], ks, wa1);
                fma2(acc[i][0], is2, wb0);
                fma2(acc[i][1], is2, wb1);
            }
        }
    }
    #pragma unroll
    for (int i = 0; i < 4; i++) {
        int gr = row0 + ty * 4 + i;
        if (gr >= N_ENT) break;
        float4 kgv = *(const float4*)&sKG[ty * 4 + i][tx * 4];
        float4 igv = *(const float4*)&sIG[ty * 4 + i][tx * 4];
        float s0, s1, s2, s3;
        unpack2(acc[i][0], s0, s1);
        unpack2(acc[i][1], s2, s3);
        float4 o;
        float g;
        g = 1.f / (1.f + __expf(-s0)); o.x = g * kgv.x + (1.f - g) * igv.x;
        g = 1.f / (1.f + __expf(-s1)); o.y = g * kgv.y + (1.f - g) * igv.y;
        g = 1.f / (1.f + __expf(-s2)); o.z = g * kgv.z + (1.f - g) * igv.z;
        g = 1.f / (1.f + __expf(-s3)); o.w = g * kgv.w + (1.f - g) * igv.w;
        *(uint2*)((char*)d_xy16[cur ^ 1] + (size_t)gr * 128 + tx * 8) =
            pack_h4(o.x, o.y, o.z, o.w);
        float4* as = (float4*)(d_sum + (size_t)gr * 64 + tx * 4);
        float4 a = *as;
        a.x += igv.x; a.y += igv.y; a.z += igv.z; a.w += igv.w;
        *as = a;
    }
}

// ====== Launch 9: final score GEMM + re-zero counters for the next graph replay ==========
__global__ void k_final(const int* __restrict__ uids, const int* __restrict__ iids,
                        float* __restrict__ out) {
    int bid = blockIdx.x;
    int tx = threadIdx.x, ty = threadIdx.y;
    if (bid >= 8192) {
        int t = ty * 16 + tx;
        int i = (bid - 8192) * 256 + t;
        if (i < N_ENT) d_kg_cnt[i] = 0;
        else {
            i -= N_ENT;
            if (i < N_TOT) d_ain_cnt[i] = 0;
        }
        return;
    }
    __shared__ float sU[16][68];
    __shared__ float sI[16][68];
    int ix = bid & 127, iy = bid >> 7;
    int u0 = iy * 16, i0 = ix * 16;
    {
        int ur = uids[u0 + ty];
        *(float4*)&sU[ty][tx * 4] = *(const float4*)(d_sum + (size_t)ur * 64 + tx * 4);
        int ir = iids[i0 + ty];
        *(float4*)&sI[ty][tx * 4] = *(const float4*)(d_sum + (size_t)ir * 64 + tx * 4);
    }
    __syncthreads();
    float acc = 0.f;
    #pragma unroll
    for (int k = 0; k < 64; k++) acc += sU[ty][k] * sI[tx][k];
    out[(size_t)(u0 + ty) * 2048 + i0 + tx] = acc;
}

// ---------------- launch ----------------
extern "C" void kernel_launch(void* const* d_in, const int* in_sizes, int n_in,
                              void* d_out, int out_size) {
    const float* E0   = (const float*)d_in[0];
    const float* rel  = (const float*)d_in[1];
    const float* Wk   = (const float*)d_in[2];
    const float* Wkb  = (const float*)d_in[3];
    const float* Wa   = (const float*)d_in[4];
    const float* Wb   = (const float*)d_in[5];
    const int*   kg_h = (const int*)d_in[6];
    const int*   kg_t = (const int*)d_in[7];
    const int*   kg_r = (const int*)d_in[8];
    const int*   a_r  = (const int*)d_in[9];
    const int*   a_c  = (const int*)d_in[10];
    const float* a_v  = (const float*)d_in[11];
    const int*   uids = (const int*)d_in[12];
    const int*   iids = (const int*)d_in[13];
    float* out = (float*)d_out;

    // 0: hist+init+PQ+spine   1: atbt+scan   2: scatter (atomic-free)
    k_setup<<<B_H + B_I + B_P + B_S, 256>>>(E0, Wk, Wkb, rel, kg_h, a_r);
    k_atbt_scan<<<B_ATBT + NB_KG + NB_AIN, 1024>>>(E0);
    k_scatter<<<B_H, 256>>>(kg_h, kg_t, kg_r, a_r, a_c, a_v);

    int cur = 0;
    for (int l = 0; l < 3; l++) {
        // 3,5,7: spmm  (launch idx 3 -> ncu profiles the new spmm next round)
        k_spmm<<<15625, 256>>>(cur);
        // 4,6,8: fusion + users
        k_fusion_users<<<NBF + (N_USR * 16 + 255) / 256, 256>>>(Wa, Wb, cur);
        cur ^= 1;
    }

    dim3 fb(16, 16);
    k_final<<<8192 + 977, fb>>>(uids, iids, out);
    (void)in_sizes; (void)n_in; (void)out_size;
}

// round 13
// speedup vs baseline: 1.1242x; 1.1242x over previous
#include <cuda_runtime.h>
#include <cuda_fp16.h>
#include <math.h>

#define N_ENT 100000
#define N_USR 50000
#define N_TOT 150000
#define DIM 64
#define E_KG 1500000
#define E_CF 1500000
#define LEAKY 0.01f

#define NB_KG 98    // ceil(100000/1024)
#define NB_AIN 147  // ceil(150000/1024)
#define NBF 1563    // ceil(100000/64)

#define B_H 11719   // ceil(3,000,000/256) edge hist
#define B_I 9375    // N_TOT*16/256 init float4
#define B_P 9       // PQ + cr
#define B_Z 393     // rowsum + spine zero
#define B_ATBT 1563

// ---------------- scratch (static device globals; zero-initialized at load) ----------------
__device__ float d_PQ[128 * 16];
__device__ float d_cr[16];
__device__ float d_At[(size_t)N_ENT * 16];
__device__ float d_Bt[(size_t)N_ENT * 16];
__device__ int   d_kg_cnt[N_ENT];
__device__ int   d_kg_rp[N_ENT + 1];
__device__ int2  d_csr_kg[E_KG];            // (tail*128 byte-offset, half2(a,a) bits)
__device__ float d_rowsum[N_ENT];
__device__ int   d_ain_cnt[N_TOT];
__device__ int   d_ain_rp[N_TOT + 1];
__device__ int2  d_csr_ain[E_CF];           // (col*128 byte-offset, half2(v,v) bits)
__device__ unsigned d_spine[512];
__device__ __align__(16) __half2 d_kg16[2][(size_t)N_ENT * 32];  // fp16 gather source (kg)
__device__ __align__(16) __half2 d_xy16[2][(size_t)N_TOT * 32];  // fp16 gather source (ain)
__device__ float d_ig[(size_t)N_TOT * DIM];                      // fp32 ain-spmm out
__device__ float d_sum[(size_t)N_TOT * DIM];

// ---------------- helpers ----------------
__device__ __forceinline__ void fma2(unsigned long long& d, unsigned long long a,
                                     unsigned long long b) {
    asm("fma.rn.f32x2 %0, %1, %2, %0;" : "+l"(d) : "l"(a), "l"(b));
}
__device__ __forceinline__ unsigned long long splat2(float x) {
    unsigned long long r;
    asm("mov.b64 %0, {%1, %1};" : "=l"(r) : "r"(__float_as_uint(x)));
    return r;
}
__device__ __forceinline__ void unpack2(unsigned long long v, float& lo, float& hi) {
    unsigned a, b;
    asm("mov.b64 {%0, %1}, %2;" : "=r"(a), "=r"(b) : "l"(v));
    lo = __uint_as_float(a);
    hi = __uint_as_float(b);
}
__device__ __forceinline__ uint2 pack_h4(float a, float b, float c, float d) {
    __half2 h0 = __floats2half2_rn(a, b);
    __half2 h1 = __floats2half2_rn(c, d);
    uint2 u;
    u.x = *(unsigned*)&h0;
    u.y = *(unsigned*)&h1;
    return u;
}
__device__ __forceinline__ __half2 u2h(unsigned u) { return *(__half2*)&u; }
__device__ __forceinline__ unsigned h2u(__half2 h) { return *(unsigned*)&h; }
// 2-wide fp16 tanh via MUFU.TANH.F16x2 (one MUFU op per TWO elements)
__device__ __forceinline__ float2 tanh2(float a, float b) {
    __half2 h = __floats2half2_rn(a, b);
    unsigned t;
    asm("tanh.approx.f16x2 %0, %1;" : "=r"(t) : "r"(h2u(h)));
    return __half22float2(u2h(t));
}

// ================= Launch 0: edge histograms ===============
__global__ void k_hist(const int* __restrict__ kgh, const int* __restrict__ ar) {
    int e = blockIdx.x * 256 + threadIdx.x;
    if (e < E_KG) {
        atomicAdd(&d_kg_cnt[kgh[e]], 1);
    } else {
        e -= E_KG;
        if (e < E_CF) atomicAdd(&d_ain_cnt[ar[e]], 1);
    }
}

// ================= Launch 1: init copies + PQ/cr + zero rowsum/spine ===============
__global__ void k_setup2(const float* __restrict__ E0, const float* __restrict__ Wk,
                         const float* __restrict__ Wkb, const float* __restrict__ rel) {
    int b = blockIdx.x, tid = threadIdx.x;
    if (b < B_I) {
        int i = b * 256 + tid;   // exactly N_TOT*16 float4s
        float4 v = ((const float4*)E0)[i];
        ((float4*)d_sum)[i] = v;
        uint2 u = pack_h4(v.x, v.y, v.z, v.w);
        ((uint2*)d_xy16[0])[i] = u;
        if (i < N_ENT * 16) ((uint2*)d_kg16[0])[i] = u;
    } else if (b < B_I + B_P) {
        int j = (b - B_I) * 256 + tid;
        if (j < 2048) {
            int jj = j >> 4, r = j & 15;
            float s = 0.f;
            #pragma unroll
            for (int d = 0; d < 64; d++) s += Wk[jj * 64 + d] * rel[r * 64 + d];
            d_PQ[jj * 16 + r] = s;
        } else if (j < 2064) {
            int r = j - 2048;
            float s = 0.f;
            #pragma unroll
            for (int d = 0; d < 64; d++) s += Wkb[d] * rel[r * 64 + d];
            d_cr[r] = s;
        }
    } else {
        int i = (b - B_I - B_P) * 256 + tid;
        if (i < N_ENT) d_rowsum[i] = 0.f;
        else {
            i -= N_ENT;
            if (i < 512) d_spine[i] = 0u;
        }
    }
}

// ================= Launch 2: At/Bt precompute + single-pass lookback scans ================
__global__ void __launch_bounds__(1024) k_atbt_scan(const float* __restrict__ E0) {
    __shared__ float sm[6144];
    int t = threadIdx.x;
    if (blockIdx.x < B_ATBT) {
        float* sPQ = sm;
        float* sE = sm + 2048;
        int nb = blockIdx.x * 64;
        for (int i = t; i < 2048; i += 1024) sPQ[i] = d_PQ[i];
        for (int i = t; i < 4096; i += 1024) {
            int rr = nb + (i >> 6);
            sE[i] = (rr < N_ENT) ? E0[(size_t)rr * 64 + (i & 63)] : 0.f;
        }
        __syncthreads();
        int ln = t >> 4, r = t & 15;
        float a = 0.f, bb = 0.f;
        #pragma unroll
        for (int j = 0; j < 64; j++) {
            float e = sE[ln * 64 + j];
            a += e * sPQ[j * 16 + r];
            bb += e * sPQ[(64 + j) * 16 + r];
        }
        int n = nb + ln;
        if (n < N_ENT) {
            d_At[(size_t)n * 16 + r] = a;
            d_Bt[(size_t)n * 16 + r] = bb;
        }
        return;
    }
    int b2 = blockIdx.x - B_ATBT;
    int which = (b2 >= NB_KG);
    int b = which ? b2 - NB_KG : b2;
    int* cnt = which ? d_ain_cnt : d_kg_cnt;
    int* rp = which ? d_ain_rp : d_kg_rp;
    int N = which ? N_TOT : N_ENT;
    int base = which ? 256 : 0;
    int* sh = (int*)sm;
    int i = b * 1024 + t;
    int v = (i < N) ? cnt[i] : 0;
    sh[t] = v;
    __syncthreads();
    for (int s = 1; s < 1024; s <<= 1) {
        int x = (t >= s) ? sh[t - s] : 0;
        __syncthreads();
        sh[t] += x;
        __syncthreads();
    }
    int agg = sh[1023];
    __shared__ int s_ex;
    if (t == 0) {
        volatile unsigned* sp = d_spine;
        if (b == 0) {
            __threadfence();
            sp[base] = (2u << 30) | (unsigned)agg;
            s_ex = 0;
        } else {
            __threadfence();
            sp[base + b] = (1u << 30) | (unsigned)agg;
            int ex = 0;
            int p = b - 1;
            while (true) {
                unsigned w;
                do { w = sp[base + p]; } while ((w >> 30) == 0u);
                ex += (int)(w & 0x3FFFFFFFu);
                if ((w >> 30) == 2u) break;
                p--;
            }
            __threadfence();
            sp[base + b] = (2u << 30) | (unsigned)(ex + agg);
            s_ex = ex;
        }
    }
    __syncthreads();
    int ex = s_ex;
    if (i < N) {
        rp[i + 1] = ex + sh[t];
        cnt[i] = ex + sh[t] - v;   // exclusive prefix -> scatter cursor
    }
    if (b == 0 && t == 0) rp[0] = 0;
}

// ========== Launch 3: merged scatter (kg: inline logit+exp+rowsum; ain plain) ==========
__global__ void k_scatter(const int* __restrict__ h, const int* __restrict__ tt_,
                          const int* __restrict__ r, const int* __restrict__ ar,
                          const int* __restrict__ ac, const float* __restrict__ av) {
    int e = blockIdx.x * blockDim.x + threadIdx.x;
    if (e < E_KG) {
        int hh = h[e], tt = tt_[e], rr = r[e];
        float l = d_At[(size_t)tt * 16 + rr] + d_Bt[(size_t)hh * 16 + rr] + d_cr[rr];
        l = (l >= 0.f) ? l : LEAKY * l;
        float ex = __expf(l);   // logits ~ N(0, 1/8): no max-subtraction needed
        atomicAdd(&d_rowsum[hh], ex);
        int p = atomicAdd(&d_kg_cnt[hh], 1);
        d_csr_kg[p] = make_int2(tt * 128, (int)h2u(__float2half2_rn(ex)));
    } else {
        int e2 = e - E_KG;
        if (e2 >= E_CF) return;
        int p = atomicAdd(&d_ain_cnt[ar[e2]], 1);
        d_csr_ain[p] = make_int2(ac[e2] * 128, (int)h2u(__float2half2_rn(av[e2])));
    }
}

// ===== Launches 4,6,8: merged SpMM — 2 rows/warp, fp16 gather, HFMA2 + group flush =====
__global__ void __launch_bounds__(256) k_spmm(int cur) {
    int gw = (blockIdx.x * 256 + threadIdx.x) >> 5;
    int lane = threadIdx.x & 31;
    int l16 = lane & 15;
    int half = lane >> 4;
    const __half2* __restrict__ X16;
    const int2* __restrict__ csr;
    const int* __restrict__ rp;
    int row;
    bool iskg = (gw < N_ENT / 2);
    if (iskg) {
        X16 = d_kg16[cur];
        csr = d_csr_kg;
        rp = d_kg_rp;
        row = gw * 2 + half;
    } else {
        int w = gw - N_ENT / 2;
        X16 = d_xy16[cur];
        csr = d_csr_ain;
        rp = d_ain_rp;
        row = w * 2 + half;
    }
    int s = rp[row], e = rp[row + 1];
    int G = (e - s + 15) >> 4;
    int Gmax = __reduce_max_sync(0xffffffffu, G);
    float ac0 = 0.f, ac1 = 0.f, ac2 = 0.f, ac3 = 0.f;
    const char* Xb = (const char*)X16;
    int loff = l16 * 8;
    const __half2 hz = __floats2half2_rn(0.f, 0.f);
    for (int g = 0; g < Gmax; g++) {
        int idx = s + g * 16 + l16;
        int off = 0;
        unsigned ab = 0;      // half2(0,0)
        if (idx < e) {
            int2 ev = csr[idx];
            off = ev.x;
            ab = (unsigned)ev.y;
        }
        int n = e - s - g * 16;
        n = max(0, min(16, n));
        int nr = __reduce_max_sync(0xffffffffu, (n + 3) & ~3);
        __half2 h0 = hz, h1 = hz, h2 = hz, h3 = hz;
        for (int j = 0; j < nr; j += 4) {
            int o0 = __shfl_sync(~0u, off, j + 0, 16), o1 = __shfl_sync(~0u, off, j + 1, 16);
            int o2 = __shfl_sync(~0u, off, j + 2, 16), o3 = __shfl_sync(~0u, off, j + 3, 16);
            unsigned b0 = __shfl_sync(~0u, ab, j + 0, 16), b1 = __shfl_sync(~0u, ab, j + 1, 16);
            unsigned b2 = __shfl_sync(~0u, ab, j + 2, 16), b3 = __shfl_sync(~0u, ab, j + 3, 16);
            uint2 r0 = *(const uint2*)(Xb + o0 + loff);
            uint2 r1 = *(const uint2*)(Xb + o1 + loff);
            uint2 r2 = *(const uint2*)(Xb + o2 + loff);
            uint2 r3 = *(const uint2*)(Xb + o3 + loff);
            h0 = __hfma2(u2h(b0), u2h(r0.x), h0);
            h1 = __hfma2(u2h(b0), u2h(r0.y), h1);
            h2 = __hfma2(u2h(b1), u2h(r1.x), h2);
            h3 = __hfma2(u2h(b1), u2h(r1.y), h3);
            h0 = __hfma2(u2h(b2), u2h(r2.x), h0);
            h1 = __hfma2(u2h(b2), u2h(r2.y), h1);
            h2 = __hfma2(u2h(b3), u2h(r3.x), h2);
            h3 = __hfma2(u2h(b3), u2h(r3.y), h3);
        }
        // flush half partials (<=8-term chains) into fp32 accumulators
        float2 f0 = __half22float2(h0), f1 = __half22float2(h1);
        float2 f2 = __half22float2(h2), f3 = __half22float2(h3);
        ac0 += f0.x + f2.x;
        ac1 += f0.y + f2.y;
        ac2 += f1.x + f3.x;
        ac3 += f1.y + f3.y;
    }
    if (iskg) {
        float sc = (e > s) ? 1.f / d_rowsum[row] : 0.f;   // fold softmax normalization
        ac0 *= sc; ac1 *= sc; ac2 *= sc; ac3 *= sc;
        *(uint2*)((char*)d_kg16[cur ^ 1] + (size_t)row * 128 + loff) =
            pack_h4(ac0, ac1, ac2, ac3);
    } else {
        *(float4*)(d_ig + (size_t)row * 64 + l16 * 4) = make_float4(ac0, ac1, ac2, ac3);
    }
}

// ===== Launches 5,7,9: fusion gate (items, f32x2 + f16x2-tanh sigmoid) + users =====
__global__ void k_fusion_users(const float* __restrict__ Wa, const float* __restrict__ Wb,
                               int cur) {
    if (blockIdx.x >= NBF) {
        int i = (blockIdx.x - NBF) * 256 + threadIdx.x;
        if (i >= N_USR * 16) return;
        const float4* src = (const float4*)(d_ig + (size_t)N_ENT * 64);
        float4 v = src[i];
        ((uint2*)(d_xy16[cur ^ 1] + (size_t)N_ENT * 32))[i] = pack_h4(v.x, v.y, v.z, v.w);
        float4* as = (float4*)(d_sum + (size_t)N_ENT * 64);
        float4 a = as[i];
        a.x += v.x; a.y += v.y; a.z += v.z; a.w += v.w;
        as[i] = a;
        return;
    }
    __shared__ float sKG[64][68];
    __shared__ float sIG[64][68];
    const char* __restrict__ KG16 = (const char*)d_kg16[cur ^ 1];
    const float* __restrict__ IG = d_ig;
    int row0 = blockIdx.x * 64;
    int tid = threadIdx.x;  // 256
    for (int i = tid; i < 1024; i += 256) {
        int r = i >> 4, c4 = (i & 15) * 4;
        int gr = row0 + r;
        float4 kgv = make_float4(0.f, 0.f, 0.f, 0.f), igv = kgv;
        if (gr < N_ENT) {
            uint2 u = *(const uint2*)(KG16 + (size_t)gr * 128 + (i & 15) * 8);
            float2 fa = __half22float2(u2h(u.x)), fb = __half22float2(u2h(u.y));
            kgv = make_float4(fa.x, fa.y, fb.x, fb.y);
            igv = *(const float4*)(IG + (size_t)gr * 64 + c4);
        }
        *(float4*)&sKG[r][c4] = kgv;
        *(float4*)&sIG[r][c4] = igv;
    }
    __syncthreads();
    int tx = tid & 15, ty = tid >> 4;
    unsigned long long acc[4][2];
    #pragma unroll
    for (int i = 0; i < 4; i++) { acc[i][0] = 0ull; acc[i][1] = 0ull; }
    const float4* WaP = (const float4*)(Wa + tx * 4);
    const float4* WbP = (const float4*)(Wb + tx * 4);
    #pragma unroll
    for (int k4 = 0; k4 < 64; k4 += 4) {
        float4 kg[4], ig[4];
        #pragma unroll
        for (int i = 0; i < 4; i++) {
            kg[i] = *(const float4*)&sKG[ty * 4 + i][k4];
            ig[i] = *(const float4*)&sIG[ty * 4 + i][k4];
        }
        #pragma unroll
        for (int kk = 0; kk < 4; kk++) {
            float4 wav = WaP[(k4 + kk) * 16];
            float4 wbv = WbP[(k4 + kk) * 16];
            unsigned long long wa0, wa1, wb0, wb1;
            asm("mov.b64 %0, {%1, %2};" : "=l"(wa0) : "f"(wav.x), "f"(wav.y));
            asm("mov.b64 %0, {%1, %2};" : "=l"(wa1) : "f"(wav.z), "f"(wav.w));
            asm("mov.b64 %0, {%1, %2};" : "=l"(wb0) : "f"(wbv.x), "f"(wbv.y));
            asm("mov.b64 %0, {%1, %2};" : "=l"(wb1) : "f"(wbv.z), "f"(wbv.w));
            #pragma unroll
            for (int i = 0; i < 4; i++) {
                unsigned long long ks = splat2(((const float*)&kg[i])[kk]);
                unsigned long long is2 = splat2(((const float*)&ig[i])[kk]);
                fma2(acc[i][0], ks, wa0);
                fma2(acc[i][1], ks, wa1);
                fma2(acc[i][0], is2, wb0);
                fma2(acc[i][1], is2, wb1);
            }
        }
    }
    #pragma unroll
    for (int i = 0; i < 4; i++) {
        int gr = row0 + ty * 4 + i;
        if (gr >= N_ENT) break;
        float4 kgv = *(const float4*)&sKG[ty * 4 + i][tx * 4];
        float4 igv = *(const float4*)&sIG[ty * 4 + i][tx * 4];
        float s0, s1, s2, s3;
        unpack2(acc[i][0], s0, s1);
        unpack2(acc[i][1], s2, s3);
        // sigmoid lerp via f16x2 tanh (MUFU/2 per 2 elems):
        //   o = g*kg + (1-g)*ig, g = sigmoid(s) = 0.5 + 0.5*tanh(s/2)
        //   => o = 0.5*(kg+ig) + tanh(s/2) * 0.5*(kg-ig)
        float2 t01 = tanh2(0.5f * s0, 0.5f * s1);
        float2 t23 = tanh2(0.5f * s2, 0.5f * s3);
        float4 o;
        o.x = fmaf(t01.x, 0.5f * (kgv.x - igv.x), 0.5f * (kgv.x + igv.x));
        o.y = fmaf(t01.y, 0.5f * (kgv.y - igv.y), 0.5f * (kgv.y + igv.y));
        o.z = fmaf(t23.x, 0.5f * (kgv.z - igv.z), 0.5f * (kgv.z + igv.z));
        o.w = fmaf(t23.y, 0.5f * (kgv.w - igv.w), 0.5f * (kgv.w + igv.w));
        *(uint2*)((char*)d_xy16[cur ^ 1] + (size_t)gr * 128 + tx * 8) =
            pack_h4(o.x, o.y, o.z, o.w);
        float4* as = (float4*)(d_sum + (size_t)gr * 64 + tx * 4);
        float4 a = *as;
        a.x += igv.x; a.y += igv.y; a.z += igv.z; a.w += igv.w;
        *as = a;
    }
}

// ====== Launch 10: final score GEMM + re-zero counters for the next graph replay ==========
__global__ void k_final(const int* __restrict__ uids, const int* __restrict__ iids,
                        float* __restrict__ out) {
    int bid = blockIdx.x;
    int tx = threadIdx.x, ty = threadIdx.y;
    if (bid >= 8192) {
        int t = ty * 16 + tx;
        int i = (bid - 8192) * 256 + t;
        if (i < N_ENT) d_kg_cnt[i] = 0;
        else {
            i -= N_ENT;
            if (i < N_TOT) d_ain_cnt[i] = 0;
        }
        return;
    }
    __shared__ float sU[16][68];
    __shared__ float sI[16][68];
    int ix = bid & 127, iy = bid >> 7;
    int u0 = iy * 16, i0 = ix * 16;
    {
        int ur = uids[u0 + ty];
        *(float4*)&sU[ty][tx * 4] = *(const float4*)(d_sum + (size_t)ur * 64 + tx * 4);
        int ir = iids[i0 + ty];
        *(float4*)&sI[ty][tx * 4] = *(const float4*)(d_sum + (size_t)ir * 64 + tx * 4);
    }
    __syncthreads();
    float acc = 0.f;
    #pragma unroll
    for (int k = 0; k < 64; k++) acc += sU[ty][k] * sI[tx][k];
    out[(size_t)(u0 + ty) * 2048 + i0 + tx] = acc;
}

// ---------------- launch ----------------
extern "C" void kernel_launch(void* const* d_in, const int* in_sizes, int n_in,
                              void* d_out, int out_size) {
    const float* E0   = (const float*)d_in[0];
    const float* rel  = (const float*)d_in[1];
    const float* Wk   = (const float*)d_in[2];
    const float* Wkb  = (const float*)d_in[3];
    const float* Wa   = (const float*)d_in[4];
    const float* Wb   = (const float*)d_in[5];
    const int*   kg_h = (const int*)d_in[6];
    const int*   kg_t = (const int*)d_in[7];
    const int*   kg_r = (const int*)d_in[8];
    const int*   a_r  = (const int*)d_in[9];
    const int*   a_c  = (const int*)d_in[10];
    const float* a_v  = (const float*)d_in[11];
    const int*   uids = (const int*)d_in[12];
    const int*   iids = (const int*)d_in[13];
    float* out = (float*)d_out;

    // 0: hist   1: init+PQ+zero   2: atbt+scan   3: scatter
    k_hist<<<B_H, 256>>>(kg_h, a_r);
    k_setup2<<<B_I + B_P + B_Z, 256>>>(E0, Wk, Wkb, rel);
    k_atbt_scan<<<B_ATBT + NB_KG + NB_AIN, 1024>>>(E0);
    k_scatter<<<B_H, 256>>>(kg_h, kg_t, kg_r, a_r, a_c, a_v);

    int cur = 0;
    for (int l = 0; l < 3; l++) {
        // 4,6,8: spmm     5,7,9: fusion
        k_spmm<<<15625, 256>>>(cur);
        k_fusion_users<<<NBF + (N_USR * 16 + 255) / 256, 256>>>(Wa, Wb, cur);
        cur ^= 1;
    }

    dim3 fb(16, 16);
    k_final<<<8192 + 977, fb>>>(uids, iids, out);
    (void)in_sizes; (void)n_in; (void)out_size;
}